// round 10
// baseline (speedup 1.0000x reference)
#include <cuda_runtime.h>
#include <math.h>
#include <stdint.h>

// Problem constants
#define BB   2
#define SS   2048
#define DD   2048
#define NH   16
#define DH   128
#define FFN  5632
#define ROWS (BB*SS)          // 4096
#define E3   (3*NH*DH)        // 6144
#define EPS  1e-5f

// ---------------------------------------------------------------------------
// Scratch (device globals; allocation-free per harness rules)
// ---------------------------------------------------------------------------
__device__ float g_x     [ROWS*DD];                 //  LN1 out
__device__ float g_qkv   [ROWS*E3];                 //  qkv (RoPE in place)
__device__ float g_ctx   [ROWS*DD];                 //  attn context
__device__ float g_h1    [ROWS*DD];                 //  hidden + attn_out
__device__ float g_x2    [ROWS*DD];                 //  LN2 out
__device__ float g_ab    [ROWS*2*FFN];              //  fc_in out
__device__ float g_gate  [ROWS*FFN];                //  silu(a)*b

// ---------------------------------------------------------------------------
// tf32 helpers
// ---------------------------------------------------------------------------
__device__ __forceinline__ float to_tf32(float x) {
    uint32_t u;
    asm("cvt.rna.tf32.f32 %0, %1;" : "=r"(u) : "f"(x));
    return __uint_as_float(u);
}

#define MMA_TF32(c0,c1,c2,c3, a0,a1,a2,a3, b0,b1)                               \
    asm volatile("mma.sync.aligned.m16n8k8.row.col.f32.tf32.tf32.f32 "          \
                 "{%0,%1,%2,%3}, {%4,%5,%6,%7}, {%8,%9}, {%0,%1,%2,%3};"        \
                 : "+f"(c0), "+f"(c1), "+f"(c2), "+f"(c3)                       \
                 : "r"(a0), "r"(a1), "r"(a2), "r"(a3), "r"(b0), "r"(b1))

// Fast exp on the FMA pipe: exp(x) = 2^(x*log2e), rn-split, deg-5 poly.
// Max rel err ~2.4e-6 on f in [-0.5,0.5]. Clamped to [-126,126] binades.
__device__ __forceinline__ float fexp(float x) {
    float t = x * 1.4426950408889634f;
    t = fmaxf(fminf(t, 126.0f), -126.0f);
    float fi = rintf(t);
    float f  = t - fi;
    float p  = 1.3333558e-3f;
    p = fmaf(p, f, 9.6181291e-3f);
    p = fmaf(p, f, 5.5504109e-2f);
    p = fmaf(p, f, 2.4022651e-1f);
    p = fmaf(p, f, 6.9314718e-1f);
    p = fmaf(p, f, 1.0f);
    int e = (int)fi;
    return p * __int_as_float((e + 127) << 23);
}

// ---------------------------------------------------------------------------
// LayerNorm: one block per row (D = 2048, 256 threads x 8 elements)
// ---------------------------------------------------------------------------
__global__ void ln_kernel(const float* __restrict__ in,
                          const float* __restrict__ gam,
                          const float* __restrict__ bet,
                          float* __restrict__ out)
{
    __shared__ float shs[8], shq[8];
    const int row = blockIdx.x;
    const int tid = threadIdx.x;
    const float* xr = in + (size_t)row * DD;

    float4 v0 = *(const float4*)(xr + tid * 4);
    float4 v1 = *(const float4*)(xr + 1024 + tid * 4);

    float s = v0.x + v0.y + v0.z + v0.w + v1.x + v1.y + v1.z + v1.w;
    float q = v0.x*v0.x + v0.y*v0.y + v0.z*v0.z + v0.w*v0.w
            + v1.x*v1.x + v1.y*v1.y + v1.z*v1.z + v1.w*v1.w;

    #pragma unroll
    for (int o = 16; o; o >>= 1) {
        s += __shfl_down_sync(0xffffffffu, s, o);
        q += __shfl_down_sync(0xffffffffu, q, o);
    }
    const int w = tid >> 5, l = tid & 31;
    if (l == 0) { shs[w] = s; shq[w] = q; }
    __syncthreads();
    if (tid == 0) {
        float ts = 0.f, tq = 0.f;
        #pragma unroll
        for (int i = 0; i < 8; i++) { ts += shs[i]; tq += shq[i]; }
        shs[0] = ts; shq[0] = tq;
    }
    __syncthreads();

    const float mean = shs[0] * (1.0f / DD);
    const float var  = shq[0] * (1.0f / DD) - mean * mean;
    const float inv  = 1.0f / sqrtf(var + EPS);

    float4 g0 = *(const float4*)(gam + tid * 4);
    float4 g1 = *(const float4*)(gam + 1024 + tid * 4);
    float4 b0 = *(const float4*)(bet + tid * 4);
    float4 b1 = *(const float4*)(bet + 1024 + tid * 4);

    float4 o0, o1;
    o0.x = (v0.x - mean) * inv * g0.x + b0.x;
    o0.y = (v0.y - mean) * inv * g0.y + b0.y;
    o0.z = (v0.z - mean) * inv * g0.z + b0.z;
    o0.w = (v0.w - mean) * inv * g0.w + b0.w;
    o1.x = (v1.x - mean) * inv * g1.x + b1.x;
    o1.y = (v1.y - mean) * inv * g1.y + b1.y;
    o1.z = (v1.z - mean) * inv * g1.z + b1.z;
    o1.w = (v1.w - mean) * inv * g1.w + b1.w;

    float* yr = out + (size_t)row * DD;
    *(float4*)(yr + tid * 4)        = o0;
    *(float4*)(yr + 1024 + tid * 4) = o1;
}

// ---------------------------------------------------------------------------
// RoPE (in place on q,k halves of qkv).
// ---------------------------------------------------------------------------
__global__ void rope_kernel(float* __restrict__ qkv, const int* __restrict__ pid)
{
    __shared__ float sinv[64];
    const int tid = threadIdx.x;
    if (tid < 64)
        sinv[tid] = (float)exp(-((double)tid / 64.0) * 9.210340371976184); // ln(1e4)
    __syncthreads();

    const int idx = blockIdx.x * 256 + tid;   // ROWS*NH*64 total, exact multiple
    const int i   = idx & 63;
    const int h   = (idx >> 6) & 15;
    const int row = idx >> 10;

    const float f = (float)pid[row] * sinv[i];
    float sv, cv;
    sincosf(f, &sv, &cv);

    const size_t base = (size_t)row * E3 + (size_t)h * 384;
    float q0 = qkv[base + i],       q1 = qkv[base + 64 + i];
    qkv[base + i]        = q0 * cv - q1 * sv;
    qkv[base + 64 + i]   = q1 * cv + q0 * sv;
    float k0 = qkv[base + 128 + i], k1 = qkv[base + 192 + i];
    qkv[base + 128 + i]  = k0 * cv - k1 * sv;
    qkv[base + 192 + i]  = k1 * cv + k0 * sv;
}

// ---------------------------------------------------------------------------
// Flash attention: per (b,h), q-block of 128 rows.
// 256 threads = 8 warps; warp w owns q rows [w*16, w*16+16).
// Q,K,V tiles tf32-rounded in smem (Q scaled by 1/sqrt(DH)).
// Online softmax with fast FMA-pipe exp. Output -> ctx [B*S, H*DH].
// ---------------------------------------------------------------------------
#define FPAD 132
#define FLASH_SMEM (3 * 128 * FPAD * 4)

__global__ __launch_bounds__(256, 1)
void flash_kernel(const float* __restrict__ qkv,
                  const unsigned char* __restrict__ mask,
                  float* __restrict__ ctx)
{
    extern __shared__ float sm[];
    float* Qs = sm;                  // [q 128][d FPAD]
    float* Ks = sm + 128 * FPAD;     // [d 128][key FPAD]
    float* Vs = sm + 2 * 128 * FPAD; // [key 128][d FPAD]

    const int qblk = blockIdx.x;     // 0..15
    const int bh   = blockIdx.y;     // 0..31
    const int b = bh >> 4, h = bh & 15;
    const int tid = threadIdx.x;
    const int lane = tid & 31, wid = tid >> 5;
    const int mq = lane >> 2, kq = lane & 3;

    const float scale = 0.08838834764831845f;   // 1/sqrt(128)
    const float* qbase = qkv + (size_t)(b * SS + qblk * 128) * E3 + (size_t)h * 384;

    // --- load Q tile (scaled, tf32) ---
    #pragma unroll
    for (int it = 0; it < 16; it++) {
        int idx = it * 256 + tid;          // 4096 float4s
        int r = idx >> 5, c4 = (idx & 31) * 4;
        float4 v = *(const float4*)(qbase + (size_t)r * E3 + c4);
        float4 o;
        o.x = to_tf32(v.x * scale); o.y = to_tf32(v.y * scale);
        o.z = to_tf32(v.z * scale); o.w = to_tf32(v.w * scale);
        *(float4*)(Qs + r * FPAD + c4) = o;
    }

    float m0 = -1e30f, m1 = -1e30f, l0 = 0.f, l1 = 0.f;
    float O[16][4];
    #pragma unroll
    for (int d = 0; d < 16; d++)
        #pragma unroll
        for (int c = 0; c < 4; c++) O[d][c] = 0.f;

    const int qrow = wid * 16 + mq;   // local q row for this thread

    for (int kb = 0; kb < 16; kb++) {
        __syncthreads();   // previous iteration's reads done before overwrite

        // --- load K tile transposed: Ks[d][key], tf32 ---
        {
            const float* kbase = qkv + (size_t)(b * SS + kb * 128) * E3
                               + (size_t)h * 384 + 128;
            const int ar = tid >> 2;            // key 0..63
            const int ac = (tid & 3) * 4;       // d sub-offset
            #pragma unroll
            for (int half = 0; half < 2; half++) {
                const float* kb0 = kbase + (size_t)(ar + 64 * half) * E3;
                #pragma unroll
                for (int ch = 0; ch < 128; ch += 16) {
                    float4 v = *(const float4*)(kb0 + ch + ac);
                    int dbase = ch + ac;
                    int keyi  = ar + 64 * half;
                    Ks[(dbase + 0) * FPAD + keyi] = to_tf32(v.x);
                    Ks[(dbase + 1) * FPAD + keyi] = to_tf32(v.y);
                    Ks[(dbase + 2) * FPAD + keyi] = to_tf32(v.z);
                    Ks[(dbase + 3) * FPAD + keyi] = to_tf32(v.w);
                }
            }
        }
        // --- load V tile direct: Vs[key][d], tf32 ---
        {
            const float* vbase = qkv + (size_t)(b * SS + kb * 128) * E3
                               + (size_t)h * 384 + 256;
            #pragma unroll
            for (int it = 0; it < 16; it++) {
                int idx = it * 256 + tid;
                int r = idx >> 5, c4 = (idx & 31) * 4;
                float4 v = *(const float4*)(vbase + (size_t)r * E3 + c4);
                float4 o;
                o.x = to_tf32(v.x); o.y = to_tf32(v.y);
                o.z = to_tf32(v.z); o.w = to_tf32(v.w);
                *(float4*)(Vs + r * FPAD + c4) = o;
            }
        }
        __syncthreads();

        // --- S = Q K^T (scaled) ---
        float S[16][4];
        #pragma unroll
        for (int t = 0; t < 16; t++)
            #pragma unroll
            for (int c = 0; c < 4; c++) S[t][c] = 0.f;

        #pragma unroll
        for (int k8 = 0; k8 < 16; k8++) {
            const int kr = k8 * 8 + kq;
            uint32_t a0 = __float_as_uint(Qs[(size_t)qrow * FPAD + kr]);
            uint32_t a1 = __float_as_uint(Qs[(size_t)(qrow + 8) * FPAD + kr]);
            uint32_t a2 = __float_as_uint(Qs[(size_t)qrow * FPAD + kr + 4]);
            uint32_t a3 = __float_as_uint(Qs[(size_t)(qrow + 8) * FPAD + kr + 4]);
            #pragma unroll
            for (int t = 0; t < 16; t++) {
                uint32_t b0 = __float_as_uint(Ks[(size_t)kr * FPAD + t * 8 + mq]);
                uint32_t b1 = __float_as_uint(Ks[(size_t)(kr + 4) * FPAD + t * 8 + mq]);
                MMA_TF32(S[t][0], S[t][1], S[t][2], S[t][3],
                         a0, a1, a2, a3, b0, b1);
            }
        }

        // --- mask ---
        {
            const unsigned char* mbase = mask + (size_t)b * SS * SS
                + (size_t)(qblk * 128 + qrow) * SS + kb * 128;
            const unsigned char* mbase8 = mbase + (size_t)8 * SS;
            #pragma unroll
            for (int t = 0; t < 16; t++) {
                uchar2 u0 = *(const uchar2*)(mbase  + t * 8 + 2 * kq);
                uchar2 u1 = *(const uchar2*)(mbase8 + t * 8 + 2 * kq);
                if (u0.x) S[t][0] = -10000.f;
                if (u0.y) S[t][1] = -10000.f;
                if (u1.x) S[t][2] = -10000.f;
                if (u1.y) S[t][3] = -10000.f;
            }
        }

        // --- online softmax update ---
        float mi0 = -1e30f, mi1 = -1e30f;
        #pragma unroll
        for (int t = 0; t < 16; t++) {
            mi0 = fmaxf(mi0, fmaxf(S[t][0], S[t][1]));
            mi1 = fmaxf(mi1, fmaxf(S[t][2], S[t][3]));
        }
        mi0 = fmaxf(mi0, __shfl_xor_sync(0xffffffffu, mi0, 1));
        mi0 = fmaxf(mi0, __shfl_xor_sync(0xffffffffu, mi0, 2));
        mi1 = fmaxf(mi1, __shfl_xor_sync(0xffffffffu, mi1, 1));
        mi1 = fmaxf(mi1, __shfl_xor_sync(0xffffffffu, mi1, 2));

        const float mn0 = fmaxf(m0, mi0);
        const float mn1 = fmaxf(m1, mi1);
        const float f0 = fexp(m0 - mn0);
        const float f1 = fexp(m1 - mn1);
        m0 = mn0; m1 = mn1;

        float s0 = 0.f, s1 = 0.f;
        #pragma unroll
        for (int t = 0; t < 16; t++) {
            float p;
            p = fexp(S[t][0] - mn0); s0 += p; S[t][0] = to_tf32(p);
            p = fexp(S[t][1] - mn0); s0 += p; S[t][1] = to_tf32(p);
            p = fexp(S[t][2] - mn1); s1 += p; S[t][2] = to_tf32(p);
            p = fexp(S[t][3] - mn1); s1 += p; S[t][3] = to_tf32(p);
        }
        s0 += __shfl_xor_sync(0xffffffffu, s0, 1);
        s0 += __shfl_xor_sync(0xffffffffu, s0, 2);
        s1 += __shfl_xor_sync(0xffffffffu, s1, 1);
        s1 += __shfl_xor_sync(0xffffffffu, s1, 2);
        l0 = l0 * f0 + s0;
        l1 = l1 * f1 + s1;

        #pragma unroll
        for (int d = 0; d < 16; d++) {
            O[d][0] *= f0; O[d][1] *= f0;
            O[d][2] *= f1; O[d][3] *= f1;
        }

        // --- O += P V  (convert P output-frags to A-frags via shuffles) ---
        const int srcA = (lane & ~3) | (kq >> 1);
        const int srcB = srcA + 2;
        const bool odd = (kq & 1);
        #pragma unroll
        for (int j = 0; j < 16; j++) {
            float sA0 = __shfl_sync(0xffffffffu, S[j][0], srcA);
            float sA1 = __shfl_sync(0xffffffffu, S[j][1], srcA);
            float sA2 = __shfl_sync(0xffffffffu, S[j][2], srcA);
            float sA3 = __shfl_sync(0xffffffffu, S[j][3], srcA);
            float sB0 = __shfl_sync(0xffffffffu, S[j][0], srcB);
            float sB1 = __shfl_sync(0xffffffffu, S[j][1], srcB);
            float sB2 = __shfl_sync(0xffffffffu, S[j][2], srcB);
            float sB3 = __shfl_sync(0xffffffffu, S[j][3], srcB);
            uint32_t a0 = __float_as_uint(odd ? sA1 : sA0);
            uint32_t a1 = __float_as_uint(odd ? sA3 : sA2);
            uint32_t a2 = __float_as_uint(odd ? sB1 : sB0);
            uint32_t a3 = __float_as_uint(odd ? sB3 : sB2);
            const int krow = j * 8 + kq;
            #pragma unroll
            for (int d = 0; d < 16; d++) {
                uint32_t b0 = __float_as_uint(Vs[(size_t)krow * FPAD + d * 8 + mq]);
                uint32_t b1 = __float_as_uint(Vs[(size_t)(krow + 4) * FPAD + d * 8 + mq]);
                MMA_TF32(O[d][0], O[d][1], O[d][2], O[d][3],
                         a0, a1, a2, a3, b0, b1);
            }
        }
    }

    // --- epilogue: O / l -> ctx ---
    const float inv0 = 1.0f / l0;
    const float inv1 = 1.0f / l1;
    const size_t r0 = (size_t)(b * SS + qblk * 128 + qrow);
    float* c0row = ctx + r0 * DD + h * DH;
    float* c1row = c0row + (size_t)8 * DD;
    #pragma unroll
    for (int d = 0; d < 16; d++) {
        const int col = d * 8 + 2 * kq;
        float2 o0, o1;
        o0.x = O[d][0] * inv0; o0.y = O[d][1] * inv0;
        o1.x = O[d][2] * inv1; o1.y = O[d][3] * inv1;
        *(float2*)(c0row + col) = o0;
        *(float2*)(c1row + col) = o1;
    }
}

// ---------------------------------------------------------------------------
// SwiGLU: g = silu(a) * b   (fast exp on FMA pipe)
// ---------------------------------------------------------------------------
__global__ void swiglu_kernel(const float* __restrict__ ab, float* __restrict__ g)
{
    const int c = blockIdx.x * 256 + threadIdx.x;   // FFN = 22*256 exact
    const int r = blockIdx.y;
    const size_t base = (size_t)r * (2 * FFN);
    const float a = ab[base + c];
    const float b = ab[base + FFN + c];
    g[(size_t)r * FFN + c] = (a / (1.0f + fexp(-a))) * b;
}

// ---------------------------------------------------------------------------
// TF32 tensor-core GEMM: C = alpha * A(.)B (+ R)
// 128x128x16 CTA tile, 256 threads = 8 warps, each warp 64x32 via m16n8k8.
// ---------------------------------------------------------------------------
#define SPAD 136

template<bool TRANSB>
__global__ __launch_bounds__(256, 2)
void gemm_tc(int M, int N, int K,
             const float* __restrict__ A, int lda, long long sAb, long long sAh,
             const float* __restrict__ B, int ldb, long long sBb, long long sBh,
             float*       __restrict__ C, int ldc, long long sCb, long long sCh,
             const float* __restrict__ R,
             float alpha, int nh)
{
    __shared__ float As[2][16][SPAD];
    __shared__ float Bs[2][16][SPAD];

    const int z  = blockIdx.z;
    const int zb = z / nh, zh = z % nh;
    A += (size_t)zb * sAb + (size_t)zh * sAh;
    B += (size_t)zb * sBb + (size_t)zh * sBh;
    C += (size_t)zb * sCb + (size_t)zh * sCh;
    if (R) R += (size_t)zb * sCb + (size_t)zh * sCh;

    const int m0  = blockIdx.y * 128;
    const int n0  = blockIdx.x * 128;
    const int tid = threadIdx.x;
    const int lane = tid & 31;
    const int wid  = tid >> 5;
    const int wm = (wid >> 2) * 64;
    const int wn = (wid & 3) * 32;

    const int ar = tid >> 2;
    const int ac = (tid & 3) << 2;
    const int br = tid >> 5;
    const int bc = (tid & 31) << 2;

    const float* Ag0 = A + (size_t)(m0 + ar) * lda + ac;
    const float* Ag1 = A + (size_t)(m0 + ar + 64) * lda + ac;
    const float* Bg0;
    const float* Bg1;
    if (TRANSB) {
        Bg0 = B + (size_t)(n0 + ar) * ldb + ac;
        Bg1 = B + (size_t)(n0 + ar + 64) * ldb + ac;
    } else {
        Bg0 = B + (size_t)br * ldb + n0 + bc;
        Bg1 = B + (size_t)(br + 8) * ldb + n0 + bc;
    }

    float acc[4][4][4];
    #pragma unroll
    for (int i = 0; i < 4; i++)
        #pragma unroll
        for (int j = 0; j < 4; j++)
            #pragma unroll
            for (int c = 0; c < 4; c++) acc[i][j][c] = 0.f;

    float4 ra0, ra1, rb0, rb1;

#define LOAD_TILE(kt) do {                                                          \
        ra0 = *(const float4*)(Ag0 + (size_t)(kt) * 16);                            \
        ra1 = *(const float4*)(Ag1 + (size_t)(kt) * 16);                            \
        if (TRANSB) {                                                               \
            rb0 = *(const float4*)(Bg0 + (size_t)(kt) * 16);                        \
            rb1 = *(const float4*)(Bg1 + (size_t)(kt) * 16);                        \
        } else {                                                                    \
            rb0 = *(const float4*)(Bg0 + (size_t)(kt) * 16 * ldb);                  \
            rb1 = *(const float4*)(Bg1 + (size_t)(kt) * 16 * ldb);                  \
        }                                                                           \
    } while (0)

#define STORE_TILE(buf) do {                                                        \
        As[buf][ac+0][ar]    = to_tf32(ra0.x); As[buf][ac+1][ar]    = to_tf32(ra0.y);\
        As[buf][ac+2][ar]    = to_tf32(ra0.z); As[buf][ac+3][ar]    = to_tf32(ra0.w);\
        As[buf][ac+0][ar+64] = to_tf32(ra1.x); As[buf][ac+1][ar+64] = to_tf32(ra1.y);\
        As[buf][ac+2][ar+64] = to_tf32(ra1.z); As[buf][ac+3][ar+64] = to_tf32(ra1.w);\
        if (TRANSB) {                                                               \
            Bs[buf][ac+0][ar]    = to_tf32(rb0.x); Bs[buf][ac+1][ar]    = to_tf32(rb0.y);\
            Bs[buf][ac+2][ar]    = to_tf32(rb0.z); Bs[buf][ac+3][ar]    = to_tf32(rb0.w);\
            Bs[buf][ac+0][ar+64] = to_tf32(rb1.x); Bs[buf][ac+1][ar+64] = to_tf32(rb1.y);\
            Bs[buf][ac+2][ar+64] = to_tf32(rb1.z); Bs[buf][ac+3][ar+64] = to_tf32(rb1.w);\
        } else {                                                                    \
            float4 t0, t1;                                                          \
            t0.x = to_tf32(rb0.x); t0.y = to_tf32(rb0.y);                           \
            t0.z = to_tf32(rb0.z); t0.w = to_tf32(rb0.w);                           \
            t1.x = to_tf32(rb1.x); t1.y = to_tf32(rb1.y);                           \
            t1.z = to_tf32(rb1.z); t1.w = to_tf32(rb1.w);                           \
            *(float4*)&Bs[buf][br][bc]     = t0;                                    \
            *(float4*)&Bs[buf][br + 8][bc] = t1;                                    \
        }                                                                           \
    } while (0)

    const int T = K >> 4;
    LOAD_TILE(0);
    STORE_TILE(0);
    __syncthreads();

    const int kq = lane & 3;
    const int mq = lane >> 2;

    for (int t = 0; t < T; ++t) {
        const int cur = t & 1;
        if (t + 1 < T) LOAD_TILE(t + 1);

        #pragma unroll
        for (int k8 = 0; k8 < 16; k8 += 8) {
            const int kr = k8 + kq;
            uint32_t af[4][4], bf[4][2];
            #pragma unroll
            for (int mi = 0; mi < 4; mi++) {
                const int mb = wm + mi * 16 + mq;
                af[mi][0] = __float_as_uint(As[cur][kr][mb]);
                af[mi][1] = __float_as_uint(As[cur][kr][mb + 8]);
                af[mi][2] = __float_as_uint(As[cur][kr + 4][mb]);
                af[mi][3] = __float_as_uint(As[cur][kr + 4][mb + 8]);
            }
            #pragma unroll
            for (int nj = 0; nj < 4; nj++) {
                const int nb = wn + nj * 8 + mq;
                bf[nj][0] = __float_as_uint(Bs[cur][kr][nb]);
                bf[nj][1] = __float_as_uint(Bs[cur][kr + 4][nb]);
            }
            #pragma unroll
            for (int mi = 0; mi < 4; mi++)
                #pragma unroll
                for (int nj = 0; nj < 4; nj++)
                    MMA_TF32(acc[mi][nj][0], acc[mi][nj][1],
                             acc[mi][nj][2], acc[mi][nj][3],
                             af[mi][0], af[mi][1], af[mi][2], af[mi][3],
                             bf[nj][0], bf[nj][1]);
        }

        if (t + 1 < T) {
            STORE_TILE(cur ^ 1);
            __syncthreads();
        }
    }

#undef LOAD_TILE
#undef STORE_TILE

    #pragma unroll
    for (int mi = 0; mi < 4; mi++) {
        #pragma unroll
        for (int half = 0; half < 2; half++) {
            const int m = m0 + wm + mi * 16 + mq + half * 8;
            float* crow = C + (size_t)m * ldc;
            const float* rrow = R ? R + (size_t)m * ldc : nullptr;
            #pragma unroll
            for (int nj = 0; nj < 4; nj++) {
                const int n = n0 + wn + nj * 8 + 2 * kq;
                float2 o;
                o.x = alpha * acc[mi][nj][half * 2 + 0];
                o.y = alpha * acc[mi][nj][half * 2 + 1];
                if (R) {
                    float2 rv = *(const float2*)(rrow + n);
                    o.x += rv.x; o.y += rv.y;
                }
                *(float2*)(crow + n) = o;
            }
        }
    }
}

// ---------------------------------------------------------------------------
// Launch
// ---------------------------------------------------------------------------
extern "C" void kernel_launch(void* const* d_in, const int* in_sizes, int n_in,
                              void* d_out, int out_size)
{
    const float*         hidden = (const float*)d_in[0];
    const unsigned char* mask   = (const unsigned char*)d_in[1];
    const int*           pos    = (const int*)d_in[2];
    const float*         ln1g   = (const float*)d_in[3];
    const float*         ln1b   = (const float*)d_in[4];
    const float*         Wqkv   = (const float*)d_in[5];
    const float*         Wo     = (const float*)d_in[6];
    const float*         ln2g   = (const float*)d_in[7];
    const float*         ln2b   = (const float*)d_in[8];
    const float*         Wfi    = (const float*)d_in[9];
    const float*         Wfo    = (const float*)d_in[10];
    float*               out    = (float*)d_out;

    float *x, *qkv, *ctx, *h1, *x2, *ab, *gt;
    cudaGetSymbolAddress((void**)&x,   g_x);
    cudaGetSymbolAddress((void**)&qkv, g_qkv);
    cudaGetSymbolAddress((void**)&ctx, g_ctx);
    cudaGetSymbolAddress((void**)&h1,  g_h1);
    cudaGetSymbolAddress((void**)&x2,  g_x2);
    cudaGetSymbolAddress((void**)&ab,  g_ab);
    cudaGetSymbolAddress((void**)&gt,  g_gate);

    cudaFuncSetAttribute(flash_kernel,
                         cudaFuncAttributeMaxDynamicSharedMemorySize, FLASH_SMEM);

    // 1) LN1
    ln_kernel<<<ROWS, 256>>>(hidden, ln1g, ln1b, x);

    // 2) qkv = x @ Wqkv   [4096,6144]
    gemm_tc<false><<<dim3(E3 / 128, ROWS / 128, 1), 256>>>(
        ROWS, E3, DD, x, DD, 0, 0, Wqkv, E3, 0, 0, qkv, E3, 0, 0,
        nullptr, 1.0f, 1);

    // 3) RoPE on q,k (in place)
    rope_kernel<<<(ROWS * NH * 64) / 256, 256>>>(qkv, pos);

    // 4) fused attention (QK^T + mask + softmax + PV) -> ctx
    flash_kernel<<<dim3(SS / 128, BB * NH), 256, FLASH_SMEM>>>(qkv, mask, ctx);

    // 5) h1 = hidden + ctx @ Wo
    gemm_tc<false><<<dim3(DD / 128, ROWS / 128, 1), 256>>>(
        ROWS, DD, DD, ctx, DD, 0, 0, Wo, DD, 0, 0, h1, DD, 0, 0,
        hidden, 1.0f, 1);

    // 6) LN2
    ln_kernel<<<ROWS, 256>>>(h1, ln2g, ln2b, x2);

    // 7) ab = x2 @ Wfc_in   [4096,11264]
    gemm_tc<false><<<dim3((2 * FFN) / 128, ROWS / 128, 1), 256>>>(
        ROWS, 2 * FFN, DD, x2, DD, 0, 0, Wfi, 2 * FFN, 0, 0, ab, 2 * FFN, 0, 0,
        nullptr, 1.0f, 1);

    // 8) gate = silu(a) * b
    swiglu_kernel<<<dim3(FFN / 256, ROWS), 256>>>(ab, gt);

    // 9) out = h1 + gate @ Wfc_out
    gemm_tc<false><<<dim3(DD / 128, ROWS / 128, 1), 256>>>(
        ROWS, DD, FFN, gt, FFN, 0, 0, Wfo, DD, 0, 0, out, DD, 0, 0,
        h1, 1.0f, 1);

    (void)in_sizes; (void)n_in; (void)out_size;
}

// round 14
// speedup vs baseline: 1.0579x; 1.0579x over previous
#include <cuda_runtime.h>
#include <math.h>
#include <stdint.h>

// Problem constants
#define BB   2
#define SS   2048
#define DD   2048
#define NH   16
#define DH   128
#define FFN  5632
#define ROWS (BB*SS)          // 4096
#define E3   (3*NH*DH)        // 6144
#define EPS  1e-5f

// ---------------------------------------------------------------------------
// Scratch (device globals; allocation-free per harness rules)
// ---------------------------------------------------------------------------
__device__ float g_x     [ROWS*DD];                 //  LN1 out
__device__ float g_qkv   [ROWS*E3];                 //  qkv (RoPE in place)
__device__ float g_ctx   [ROWS*DD];                 //  attn context
__device__ float g_h1    [ROWS*DD];                 //  hidden + attn_out
__device__ float g_x2    [ROWS*DD];                 //  LN2 out
__device__ float g_ab    [ROWS*2*FFN];              //  fc_in out
__device__ float g_gate  [ROWS*FFN];                //  silu(a)*b

// ---------------------------------------------------------------------------
// tf32 helpers
// ---------------------------------------------------------------------------
__device__ __forceinline__ float to_tf32(float x) {
    uint32_t u;
    asm("cvt.rna.tf32.f32 %0, %1;" : "=r"(u) : "f"(x));
    return __uint_as_float(u);
}

#define MMA_TF32(c0,c1,c2,c3, a0,a1,a2,a3, b0,b1)                               \
    asm volatile("mma.sync.aligned.m16n8k8.row.col.f32.tf32.tf32.f32 "          \
                 "{%0,%1,%2,%3}, {%4,%5,%6,%7}, {%8,%9}, {%0,%1,%2,%3};"        \
                 : "+f"(c0), "+f"(c1), "+f"(c2), "+f"(c3)                       \
                 : "r"(a0), "r"(a1), "r"(a2), "r"(a3), "r"(b0), "r"(b1))

// Fast exp on the FMA pipe (deg-5 poly in 2^f), max rel err ~2.4e-6.
__device__ __forceinline__ float fexp(float x) {
    float t = x * 1.4426950408889634f;
    t = fmaxf(fminf(t, 126.0f), -126.0f);
    float fi = rintf(t);
    float f  = t - fi;
    float p  = 1.3333558e-3f;
    p = fmaf(p, f, 9.6181291e-3f);
    p = fmaf(p, f, 5.5504109e-2f);
    p = fmaf(p, f, 2.4022651e-1f);
    p = fmaf(p, f, 6.9314718e-1f);
    p = fmaf(p, f, 1.0f);
    int e = (int)fi;
    return p * __int_as_float((e + 127) << 23);
}

// ---------------------------------------------------------------------------
// LayerNorm: one block per row
// ---------------------------------------------------------------------------
__global__ void ln_kernel(const float* __restrict__ in,
                          const float* __restrict__ gam,
                          const float* __restrict__ bet,
                          float* __restrict__ out)
{
    __shared__ float shs[8], shq[8];
    const int row = blockIdx.x;
    const int tid = threadIdx.x;
    const float* xr = in + (size_t)row * DD;

    float4 v0 = *(const float4*)(xr + tid * 4);
    float4 v1 = *(const float4*)(xr + 1024 + tid * 4);

    float s = v0.x + v0.y + v0.z + v0.w + v1.x + v1.y + v1.z + v1.w;
    float q = v0.x*v0.x + v0.y*v0.y + v0.z*v0.z + v0.w*v0.w
            + v1.x*v1.x + v1.y*v1.y + v1.z*v1.z + v1.w*v1.w;

    #pragma unroll
    for (int o = 16; o; o >>= 1) {
        s += __shfl_down_sync(0xffffffffu, s, o);
        q += __shfl_down_sync(0xffffffffu, q, o);
    }
    const int w = tid >> 5, l = tid & 31;
    if (l == 0) { shs[w] = s; shq[w] = q; }
    __syncthreads();
    if (tid == 0) {
        float ts = 0.f, tq = 0.f;
        #pragma unroll
        for (int i = 0; i < 8; i++) { ts += shs[i]; tq += shq[i]; }
        shs[0] = ts; shq[0] = tq;
    }
    __syncthreads();

    const float mean = shs[0] * (1.0f / DD);
    const float var  = shq[0] * (1.0f / DD) - mean * mean;
    const float inv  = 1.0f / sqrtf(var + EPS);

    float4 g0 = *(const float4*)(gam + tid * 4);
    float4 g1 = *(const float4*)(gam + 1024 + tid * 4);
    float4 b0 = *(const float4*)(bet + tid * 4);
    float4 b1 = *(const float4*)(bet + 1024 + tid * 4);

    float4 o0, o1;
    o0.x = (v0.x - mean) * inv * g0.x + b0.x;
    o0.y = (v0.y - mean) * inv * g0.y + b0.y;
    o0.z = (v0.z - mean) * inv * g0.z + b0.z;
    o0.w = (v0.w - mean) * inv * g0.w + b0.w;
    o1.x = (v1.x - mean) * inv * g1.x + b1.x;
    o1.y = (v1.y - mean) * inv * g1.y + b1.y;
    o1.z = (v1.z - mean) * inv * g1.z + b1.z;
    o1.w = (v1.w - mean) * inv * g1.w + b1.w;

    float* yr = out + (size_t)row * DD;
    *(float4*)(yr + tid * 4)        = o0;
    *(float4*)(yr + 1024 + tid * 4) = o1;
}

// ---------------------------------------------------------------------------
// RoPE (in place on q,k halves of qkv)
// ---------------------------------------------------------------------------
__global__ void rope_kernel(float* __restrict__ qkv, const int* __restrict__ pid)
{
    __shared__ float sinv[64];
    const int tid = threadIdx.x;
    if (tid < 64)
        sinv[tid] = (float)exp(-((double)tid / 64.0) * 9.210340371976184);
    __syncthreads();

    const int idx = blockIdx.x * 256 + tid;
    const int i   = idx & 63;
    const int h   = (idx >> 6) & 15;
    const int row = idx >> 10;

    const float f = (float)pid[row] * sinv[i];
    float sv, cv;
    sincosf(f, &sv, &cv);

    const size_t base = (size_t)row * E3 + (size_t)h * 384;
    float q0 = qkv[base + i],       q1 = qkv[base + 64 + i];
    qkv[base + i]        = q0 * cv - q1 * sv;
    qkv[base + 64 + i]   = q1 * cv + q0 * sv;
    float k0 = qkv[base + 128 + i], k1 = qkv[base + 192 + i];
    qkv[base + 128 + i]  = k0 * cv - k1 * sv;
    qkv[base + 192 + i]  = k1 * cv + k0 * sv;
}

// ---------------------------------------------------------------------------
// Flash attention v2: 64-q blocks, 64-key tiles, 256 threads = 8 warps,
// partner-warp d-split: warp pair (2p, 2p+1) shares q rows [p*16,p*16+16);
// each warp computes the full S tile (dup) but only its d-half of PV.
// Register budget fits 128 (2 CTAs/SM -> 16 warps).
// ---------------------------------------------------------------------------
#define QPAD 132
#define KPAD 72
#define VPAD 136
#define FLASH_SMEM ((64*QPAD + 128*KPAD + 64*VPAD) * 4)

__global__ __launch_bounds__(256, 2)
void flash_kernel(const float* __restrict__ qkv,
                  const unsigned char* __restrict__ mask,
                  float* __restrict__ ctx)
{
    extern __shared__ float sm[];
    float* Qs = sm;                            // [64 q][QPAD]
    float* Ks = sm + 64 * QPAD;                // [128 d][KPAD], cols xor-swizzled
    float* Vs = sm + 64 * QPAD + 128 * KPAD;   // [64 key][VPAD]

    const int qblk = blockIdx.x;     // 0..31
    const int bh   = blockIdx.y;     // 0..31
    const int b = bh >> 4, h = bh & 15;
    const int tid = threadIdx.x;
    const int lane = tid & 31, wid = tid >> 5;
    const int mq = lane >> 2, kq = lane & 3;
    const int qg  = wid >> 1;        // q-row group 0..3
    const int dh2 = wid & 1;         // d half

    const float scale = 0.08838834764831845f;   // 1/sqrt(128)
    const float* qbase = qkv + (size_t)(b * SS + qblk * 64) * E3 + (size_t)h * 384;

    // Q tile: 64 x 128 (scaled, tf32)
    #pragma unroll
    for (int it = 0; it < 8; it++) {
        int idx = it * 256 + tid;            // 2048 float4s
        int r = idx >> 5, c4 = (idx & 31) * 4;
        float4 v = *(const float4*)(qbase + (size_t)r * E3 + c4);
        float4 o;
        o.x = to_tf32(v.x * scale); o.y = to_tf32(v.y * scale);
        o.z = to_tf32(v.z * scale); o.w = to_tf32(v.w * scale);
        *(float4*)(Qs + r * QPAD + c4) = o;
    }

    float m0 = -1e30f, m1 = -1e30f, l0 = 0.f, l1 = 0.f;
    float O[8][4];
    #pragma unroll
    for (int d = 0; d < 8; d++)
        #pragma unroll
        for (int c = 0; c < 4; c++) O[d][c] = 0.f;

    const int qrow = qg * 16 + mq;

    for (int kb = 0; kb < 32; kb++) {
        __syncthreads();

        // K tile: 64 keys transposed -> Ks[d][key ^ swz(d)]
        {
            const float* kbase = qkv + (size_t)(b * SS + kb * 64) * E3
                               + (size_t)h * 384 + 128;
            const int key = tid >> 2;          // 0..63
            const int ac  = (tid & 3) * 4;
            const float* kp = kbase + (size_t)key * E3 + ac;
            #pragma unroll
            for (int ch = 0; ch < 128; ch += 16) {
                float4 v = *(const float4*)(kp + ch);
                float t_[4] = {v.x, v.y, v.z, v.w};
                #pragma unroll
                for (int i = 0; i < 4; i++) {
                    int d = ch + ac + i;
                    int col = key ^ (((d >> 2) & 3) << 3);
                    Ks[d * KPAD + col] = to_tf32(t_[i]);
                }
            }
        }
        // V tile: 64 x 128 direct
        {
            const float* vbase = qkv + (size_t)(b * SS + kb * 64) * E3
                               + (size_t)h * 384 + 256;
            #pragma unroll
            for (int it = 0; it < 8; it++) {
                int idx = it * 256 + tid;
                int r = idx >> 5, c4 = (idx & 31) * 4;
                float4 v = *(const float4*)(vbase + (size_t)r * E3 + c4);
                float4 o;
                o.x = to_tf32(v.x); o.y = to_tf32(v.y);
                o.z = to_tf32(v.z); o.w = to_tf32(v.w);
                *(float4*)(Vs + r * VPAD + c4) = o;
            }
        }
        __syncthreads();

        // --- S = Q K^T over 64 keys ---
        float S[8][4];
        #pragma unroll
        for (int t = 0; t < 8; t++)
            #pragma unroll
            for (int c = 0; c < 4; c++) S[t][c] = 0.f;

        #pragma unroll
        for (int k8 = 0; k8 < 16; k8++) {
            const int kr = k8 * 8 + kq;
            uint32_t a0 = __float_as_uint(Qs[qrow * QPAD + kr]);
            uint32_t a1 = __float_as_uint(Qs[(qrow + 8) * QPAD + kr]);
            uint32_t a2 = __float_as_uint(Qs[qrow * QPAD + kr + 4]);
            uint32_t a3 = __float_as_uint(Qs[(qrow + 8) * QPAD + kr + 4]);
            const int sx0 = (((2 * k8)    ) & 3) << 3;   // ((kr>>2)&3)<<3, warp-uniform
            const int sx1 = (((2 * k8) + 1) & 3) << 3;   // (((kr+4)>>2)&3)<<3
            #pragma unroll
            for (int t = 0; t < 8; t++) {
                uint32_t b0 = __float_as_uint(Ks[kr * KPAD + ((t * 8 + mq) ^ sx0)]);
                uint32_t b1 = __float_as_uint(Ks[(kr + 4) * KPAD + ((t * 8 + mq) ^ sx1)]);
                MMA_TF32(S[t][0], S[t][1], S[t][2], S[t][3],
                         a0, a1, a2, a3, b0, b1);
            }
        }

        // --- mask ---
        {
            const unsigned char* mbase = mask + (size_t)b * SS * SS
                + (size_t)(qblk * 64 + qrow) * SS + kb * 64;
            const unsigned char* mbase8 = mbase + (size_t)8 * SS;
            #pragma unroll
            for (int t = 0; t < 8; t++) {
                uchar2 u0 = *(const uchar2*)(mbase  + t * 8 + 2 * kq);
                uchar2 u1 = *(const uchar2*)(mbase8 + t * 8 + 2 * kq);
                if (u0.x) S[t][0] = -10000.f;
                if (u0.y) S[t][1] = -10000.f;
                if (u1.x) S[t][2] = -10000.f;
                if (u1.y) S[t][3] = -10000.f;
            }
        }

        // --- online softmax update (partner warps compute identical values) ---
        float mi0 = -1e30f, mi1 = -1e30f;
        #pragma unroll
        for (int t = 0; t < 8; t++) {
            mi0 = fmaxf(mi0, fmaxf(S[t][0], S[t][1]));
            mi1 = fmaxf(mi1, fmaxf(S[t][2], S[t][3]));
        }
        mi0 = fmaxf(mi0, __shfl_xor_sync(0xffffffffu, mi0, 1));
        mi0 = fmaxf(mi0, __shfl_xor_sync(0xffffffffu, mi0, 2));
        mi1 = fmaxf(mi1, __shfl_xor_sync(0xffffffffu, mi1, 1));
        mi1 = fmaxf(mi1, __shfl_xor_sync(0xffffffffu, mi1, 2));

        const float mn0 = fmaxf(m0, mi0);
        const float mn1 = fmaxf(m1, mi1);
        const float f0 = fexp(m0 - mn0);
        const float f1 = fexp(m1 - mn1);
        m0 = mn0; m1 = mn1;

        float s0 = 0.f, s1 = 0.f;
        #pragma unroll
        for (int t = 0; t < 8; t++) {
            float p;
            p = fexp(S[t][0] - mn0); s0 += p; S[t][0] = to_tf32(p);
            p = fexp(S[t][1] - mn0); s0 += p; S[t][1] = to_tf32(p);
            p = fexp(S[t][2] - mn1); s1 += p; S[t][2] = to_tf32(p);
            p = fexp(S[t][3] - mn1); s1 += p; S[t][3] = to_tf32(p);
        }
        s0 += __shfl_xor_sync(0xffffffffu, s0, 1);
        s0 += __shfl_xor_sync(0xffffffffu, s0, 2);
        s1 += __shfl_xor_sync(0xffffffffu, s1, 1);
        s1 += __shfl_xor_sync(0xffffffffu, s1, 2);
        l0 = l0 * f0 + s0;
        l1 = l1 * f1 + s1;

        #pragma unroll
        for (int d = 0; d < 8; d++) {
            O[d][0] *= f0; O[d][1] *= f0;
            O[d][2] *= f1; O[d][3] *= f1;
        }

        // --- O += P V on this warp's d-half ---
        const int srcA = (lane & ~3) | (kq >> 1);
        const int srcB = srcA + 2;
        const bool odd = (kq & 1);
        const int dbase = dh2 * 64;
        #pragma unroll
        for (int j = 0; j < 8; j++) {
            float sA0 = __shfl_sync(0xffffffffu, S[j][0], srcA);
            float sA1 = __shfl_sync(0xffffffffu, S[j][1], srcA);
            float sA2 = __shfl_sync(0xffffffffu, S[j][2], srcA);
            float sA3 = __shfl_sync(0xffffffffu, S[j][3], srcA);
            float sB0 = __shfl_sync(0xffffffffu, S[j][0], srcB);
            float sB1 = __shfl_sync(0xffffffffu, S[j][1], srcB);
            float sB2 = __shfl_sync(0xffffffffu, S[j][2], srcB);
            float sB3 = __shfl_sync(0xffffffffu, S[j][3], srcB);
            uint32_t a0 = __float_as_uint(odd ? sA1 : sA0);
            uint32_t a1 = __float_as_uint(odd ? sA3 : sA2);
            uint32_t a2 = __float_as_uint(odd ? sB1 : sB0);
            uint32_t a3 = __float_as_uint(odd ? sB3 : sB2);
            const int krow = j * 8 + kq;
            #pragma unroll
            for (int d = 0; d < 8; d++) {
                uint32_t b0 = __float_as_uint(Vs[krow * VPAD + dbase + d * 8 + mq]);
                uint32_t b1 = __float_as_uint(Vs[(krow + 4) * VPAD + dbase + d * 8 + mq]);
                MMA_TF32(O[d][0], O[d][1], O[d][2], O[d][3],
                         a0, a1, a2, a3, b0, b1);
            }
        }
    }

    // --- epilogue ---
    const float inv0 = 1.0f / l0;
    const float inv1 = 1.0f / l1;
    const size_t r0 = (size_t)(b * SS + qblk * 64 + qg * 16 + mq);
    float* c0row = ctx + r0 * DD + h * DH + dh2 * 64;
    float* c1row = c0row + (size_t)8 * DD;
    #pragma unroll
    for (int d = 0; d < 8; d++) {
        const int col = d * 8 + 2 * kq;
        float2 o0, o1;
        o0.x = O[d][0] * inv0; o0.y = O[d][1] * inv0;
        o1.x = O[d][2] * inv1; o1.y = O[d][3] * inv1;
        *(float2*)(c0row + col) = o0;
        *(float2*)(c1row + col) = o1;
    }
}

// ---------------------------------------------------------------------------
// SwiGLU: g = silu(a) * b
// ---------------------------------------------------------------------------
__global__ void swiglu_kernel(const float* __restrict__ ab, float* __restrict__ g)
{
    const int c = blockIdx.x * 256 + threadIdx.x;
    const int r = blockIdx.y;
    const size_t base = (size_t)r * (2 * FFN);
    const float a = ab[base + c];
    const float b = ab[base + FFN + c];
    g[(size_t)r * FFN + c] = (a / (1.0f + fexp(-a))) * b;
}

// ---------------------------------------------------------------------------
// TF32 GEMM v2: C = alpha*A@B (+R).  128x128x16 CTA tile, 128 threads =
// 4 warps, each warp 64x64 (1.0 LDS per MMA). A smem columns xor-swizzled
// by row-quad so the transpose stores are conflict-free; the load-side xor
// is warp-uniform so fragment loads stay conflict-free.
// A: [M,K] row-major, B: [K,N] row-major. Dims are exact tile multiples.
// ---------------------------------------------------------------------------
#define SPAD 136

__global__ __launch_bounds__(128, 2)
void gemm_tc(int K,
             const float* __restrict__ A, int lda,
             const float* __restrict__ B, int ldb,
             float*       __restrict__ C, int ldc,
             const float* __restrict__ R, float alpha)
{
    __shared__ float As[2][16][SPAD];
    __shared__ float Bs[2][16][SPAD];

    const int m0  = blockIdx.y * 128;
    const int n0  = blockIdx.x * 128;
    const int tid = threadIdx.x;
    const int lane = tid & 31;
    const int wid  = tid >> 5;
    const int wm = (wid >> 1) * 64;
    const int wn = (wid & 1) * 64;
    const int kq = lane & 3;
    const int mq = lane >> 2;

    const int ar = tid >> 2;          // 0..31
    const int ac = (tid & 3) << 2;    // 0,4,8,12
    const int br = tid >> 5;          // 0..3
    const int bc = (tid & 31) << 2;   // 0..124

    const float* Ag0 = A + (size_t)(m0 + ar) * lda + ac;
    const float* Ag1 = Ag0 + (size_t)32 * lda;
    const float* Ag2 = Ag0 + (size_t)64 * lda;
    const float* Ag3 = Ag0 + (size_t)96 * lda;
    const float* Bg0 = B + (size_t)br * ldb + n0 + bc;
    const float* Bg1 = Bg0 + (size_t)4 * ldb;
    const float* Bg2 = Bg0 + (size_t)8 * ldb;
    const float* Bg3 = Bg0 + (size_t)12 * ldb;

    float acc[4][8][4];
    #pragma unroll
    for (int i = 0; i < 4; i++)
        #pragma unroll
        for (int j = 0; j < 8; j++)
            #pragma unroll
            for (int c = 0; c < 4; c++) acc[i][j][c] = 0.f;

    float4 ra0, ra1, ra2, ra3, rb0, rb1, rb2, rb3;

#define LOAD_TILE(kt) do {                                                      \
        ra0 = *(const float4*)(Ag0 + (size_t)(kt) * 16);                        \
        ra1 = *(const float4*)(Ag1 + (size_t)(kt) * 16);                        \
        ra2 = *(const float4*)(Ag2 + (size_t)(kt) * 16);                        \
        ra3 = *(const float4*)(Ag3 + (size_t)(kt) * 16);                        \
        rb0 = *(const float4*)(Bg0 + (size_t)(kt) * 16 * ldb);                  \
        rb1 = *(const float4*)(Bg1 + (size_t)(kt) * 16 * ldb);                  \
        rb2 = *(const float4*)(Bg2 + (size_t)(kt) * 16 * ldb);                  \
        rb3 = *(const float4*)(Bg3 + (size_t)(kt) * 16 * ldb);                  \
    } while (0)

#define STORE_A1(buf, rv, off) do {                                             \
        float t_[4] = {rv.x, rv.y, rv.z, rv.w};                                 \
        _Pragma("unroll")                                                       \
        for (int i_ = 0; i_ < 4; i_++) {                                        \
            int row_ = ac + i_;                                                 \
            int col_ = (ar ^ (((row_ >> 2) & 3) << 3)) + (off);                 \
            As[buf][row_][col_] = to_tf32(t_[i_]);                              \
        }                                                                       \
    } while (0)

#define STORE_B1(buf, rv, rrow) do {                                            \
        float4 t_;                                                              \
        t_.x = to_tf32(rv.x); t_.y = to_tf32(rv.y);                             \
        t_.z = to_tf32(rv.z); t_.w = to_tf32(rv.w);                             \
        *(float4*)&Bs[buf][rrow][bc] = t_;                                      \
    } while (0)

#define STORE_TILE(buf) do {                                                    \
        STORE_A1(buf, ra0, 0);  STORE_A1(buf, ra1, 32);                         \
        STORE_A1(buf, ra2, 64); STORE_A1(buf, ra3, 96);                         \
        STORE_B1(buf, rb0, br); STORE_B1(buf, rb1, br + 4);                     \
        STORE_B1(buf, rb2, br + 8); STORE_B1(buf, rb3, br + 12);                \
    } while (0)

    const int T = K >> 4;
    LOAD_TILE(0);
    STORE_TILE(0);
    __syncthreads();

    for (int t = 0; t < T; ++t) {
        const int cur = t & 1;
        if (t + 1 < T) LOAD_TILE(t + 1);

        #pragma unroll
        for (int k8 = 0; k8 < 16; k8 += 8) {
            const int kr  = k8 + kq;
            const int sx0 = (((k8    ) >> 2) & 3) << 3;   // warp-uniform
            const int sx1 = (((k8 + 4) >> 2) & 3) << 3;
            uint32_t af[4][4], bf[8][2];
            #pragma unroll
            for (int mi = 0; mi < 4; mi++) {
                const int mb = wm + mi * 16 + mq;
                af[mi][0] = __float_as_uint(As[cur][kr][mb ^ sx0]);
                af[mi][1] = __float_as_uint(As[cur][kr][(mb + 8) ^ sx0]);
                af[mi][2] = __float_as_uint(As[cur][kr + 4][mb ^ sx1]);
                af[mi][3] = __float_as_uint(As[cur][kr + 4][(mb + 8) ^ sx1]);
            }
            #pragma unroll
            for (int nj = 0; nj < 8; nj++) {
                const int nb = wn + nj * 8 + mq;
                bf[nj][0] = __float_as_uint(Bs[cur][kr][nb]);
                bf[nj][1] = __float_as_uint(Bs[cur][kr + 4][nb]);
            }
            #pragma unroll
            for (int mi = 0; mi < 4; mi++)
                #pragma unroll
                for (int nj = 0; nj < 8; nj++)
                    MMA_TF32(acc[mi][nj][0], acc[mi][nj][1],
                             acc[mi][nj][2], acc[mi][nj][3],
                             af[mi][0], af[mi][1], af[mi][2], af[mi][3],
                             bf[nj][0], bf[nj][1]);
        }

        if (t + 1 < T) {
            STORE_TILE(cur ^ 1);
            __syncthreads();
        }
    }

#undef LOAD_TILE
#undef STORE_TILE
#undef STORE_A1
#undef STORE_B1

    #pragma unroll
    for (int mi = 0; mi < 4; mi++) {
        #pragma unroll
        for (int half = 0; half < 2; half++) {
            const int m = m0 + wm + mi * 16 + mq + half * 8;
            float* crow = C + (size_t)m * ldc;
            const float* rrow = R ? R + (size_t)m * ldc : nullptr;
            #pragma unroll
            for (int nj = 0; nj < 8; nj++) {
                const int n = n0 + wn + nj * 8 + 2 * kq;
                float2 o;
                o.x = alpha * acc[mi][nj][half * 2 + 0];
                o.y = alpha * acc[mi][nj][half * 2 + 1];
                if (R) {
                    float2 rv = *(const float2*)(rrow + n);
                    o.x += rv.x; o.y += rv.y;
                }
                *(float2*)(crow + n) = o;
            }
        }
    }
}

// ---------------------------------------------------------------------------
// Launch
// ---------------------------------------------------------------------------
extern "C" void kernel_launch(void* const* d_in, const int* in_sizes, int n_in,
                              void* d_out, int out_size)
{
    const float*         hidden = (const float*)d_in[0];
    const unsigned char* mask   = (const unsigned char*)d_in[1];
    const int*           pos    = (const int*)d_in[2];
    const float*         ln1g   = (const float*)d_in[3];
    const float*         ln1b   = (const float*)d_in[4];
    const float*         Wqkv   = (const float*)d_in[5];
    const float*         Wo     = (const float*)d_in[6];
    const float*         ln2g   = (const float*)d_in[7];
    const float*         ln2b   = (const float*)d_in[8];
    const float*         Wfi    = (const float*)d_in[9];
    const float*         Wfo    = (const float*)d_in[10];
    float*               out    = (float*)d_out;

    float *x, *qkv, *ctx, *h1, *x2, *ab, *gt;
    cudaGetSymbolAddress((void**)&x,   g_x);
    cudaGetSymbolAddress((void**)&qkv, g_qkv);
    cudaGetSymbolAddress((void**)&ctx, g_ctx);
    cudaGetSymbolAddress((void**)&h1,  g_h1);
    cudaGetSymbolAddress((void**)&x2,  g_x2);
    cudaGetSymbolAddress((void**)&ab,  g_ab);
    cudaGetSymbolAddress((void**)&gt,  g_gate);

    cudaFuncSetAttribute(flash_kernel,
                         cudaFuncAttributeMaxDynamicSharedMemorySize, FLASH_SMEM);

    // 1) LN1
    ln_kernel<<<ROWS, 256>>>(hidden, ln1g, ln1b, x);

    // 2) qkv = x @ Wqkv
    gemm_tc<<<dim3(E3 / 128, ROWS / 128), 128>>>(
        DD, x, DD, Wqkv, E3, qkv, E3, nullptr, 1.0f);

    // 3) RoPE on q,k (in place)
    rope_kernel<<<(ROWS * NH * 64) / 256, 256>>>(qkv, pos);

    // 4) fused attention -> ctx
    flash_kernel<<<dim3(SS / 64, BB * NH), 256, FLASH_SMEM>>>(qkv, mask, ctx);

    // 5) h1 = hidden + ctx @ Wo
    gemm_tc<<<dim3(DD / 128, ROWS / 128), 128>>>(
        DD, ctx, DD, Wo, DD, h1, DD, hidden, 1.0f);

    // 6) LN2
    ln_kernel<<<ROWS, 256>>>(h1, ln2g, ln2b, x2);

    // 7) ab = x2 @ Wfc_in
    gemm_tc<<<dim3((2 * FFN) / 128, ROWS / 128), 128>>>(
        DD, x2, DD, Wfi, 2 * FFN, ab, 2 * FFN, nullptr, 1.0f);

    // 8) gate = silu(a) * b
    swiglu_kernel<<<dim3(FFN / 256, ROWS), 256>>>(ab, gt);

    // 9) out = h1 + gate @ Wfc_out
    gemm_tc<<<dim3(DD / 128, ROWS / 128), 128>>>(
        FFN, gt, FFN, Wfo, DD, out, DD, h1, 1.0f);

    (void)in_sizes; (void)n_in; (void)out_size;
}

// round 16
// speedup vs baseline: 1.1800x; 1.1155x over previous
#include <cuda_runtime.h>
#include <cuda_fp16.h>
#include <math.h>
#include <stdint.h>

// Problem constants
#define BB   2
#define SS   2048
#define DD   2048
#define NH   16
#define DH   128
#define FFN  5632
#define ROWS (BB*SS)          // 4096
#define E3   (3*NH*DH)        // 6144
#define EPS  1e-5f

// ---------------------------------------------------------------------------
// Scratch (device globals; allocation-free per harness rules)
// ---------------------------------------------------------------------------
__device__ float g_x     [ROWS*DD];                 //  LN1 out
__device__ float g_qkv   [ROWS*E3];                 //  qkv (RoPE in place)
__device__ float g_ctx   [ROWS*DD];                 //  attn context
__device__ float g_h1    [ROWS*DD];                 //  hidden + attn_out
__device__ float g_x2    [ROWS*DD];                 //  LN2 out
__device__ float g_ab    [ROWS*2*FFN];              //  fc_in out
__device__ float g_gate  [ROWS*FFN];                //  silu(a)*b

// ---------------------------------------------------------------------------
// tf32 helpers (flash kernel)
// ---------------------------------------------------------------------------
__device__ __forceinline__ float to_tf32(float x) {
    uint32_t u;
    asm("cvt.rna.tf32.f32 %0, %1;" : "=r"(u) : "f"(x));
    return __uint_as_float(u);
}

#define MMA_TF32(c0,c1,c2,c3, a0,a1,a2,a3, b0,b1)                               \
    asm volatile("mma.sync.aligned.m16n8k8.row.col.f32.tf32.tf32.f32 "          \
                 "{%0,%1,%2,%3}, {%4,%5,%6,%7}, {%8,%9}, {%0,%1,%2,%3};"        \
                 : "+f"(c0), "+f"(c1), "+f"(c2), "+f"(c3)                       \
                 : "r"(a0), "r"(a1), "r"(a2), "r"(a3), "r"(b0), "r"(b1))

// fp16 mma: m16n8k16, fp32 accumulate
#define MMA_F16(c0,c1,c2,c3, a0,a1,a2,a3, b0,b1)                                \
    asm volatile("mma.sync.aligned.m16n8k16.row.col.f32.f16.f16.f32 "           \
                 "{%0,%1,%2,%3}, {%4,%5,%6,%7}, {%8,%9}, {%0,%1,%2,%3};"        \
                 : "+f"(c0), "+f"(c1), "+f"(c2), "+f"(c3)                       \
                 : "r"(a0), "r"(a1), "r"(a2), "r"(a3), "r"(b0), "r"(b1))

// Fast exp on the FMA pipe (deg-5 poly in 2^f), max rel err ~2.4e-6.
__device__ __forceinline__ float fexp(float x) {
    float t = x * 1.4426950408889634f;
    t = fmaxf(fminf(t, 126.0f), -126.0f);
    float fi = rintf(t);
    float f  = t - fi;
    float p  = 1.3333558e-3f;
    p = fmaf(p, f, 9.6181291e-3f);
    p = fmaf(p, f, 5.5504109e-2f);
    p = fmaf(p, f, 2.4022651e-1f);
    p = fmaf(p, f, 6.9314718e-1f);
    p = fmaf(p, f, 1.0f);
    int e = (int)fi;
    return p * __int_as_float((e + 127) << 23);
}

// ---------------------------------------------------------------------------
// LayerNorm: one block per row
// ---------------------------------------------------------------------------
__global__ void ln_kernel(const float* __restrict__ in,
                          const float* __restrict__ gam,
                          const float* __restrict__ bet,
                          float* __restrict__ out)
{
    __shared__ float shs[8], shq[8];
    const int row = blockIdx.x;
    const int tid = threadIdx.x;
    const float* xr = in + (size_t)row * DD;

    float4 v0 = *(const float4*)(xr + tid * 4);
    float4 v1 = *(const float4*)(xr + 1024 + tid * 4);

    float s = v0.x + v0.y + v0.z + v0.w + v1.x + v1.y + v1.z + v1.w;
    float q = v0.x*v0.x + v0.y*v0.y + v0.z*v0.z + v0.w*v0.w
            + v1.x*v1.x + v1.y*v1.y + v1.z*v1.z + v1.w*v1.w;

    #pragma unroll
    for (int o = 16; o; o >>= 1) {
        s += __shfl_down_sync(0xffffffffu, s, o);
        q += __shfl_down_sync(0xffffffffu, q, o);
    }
    const int w = tid >> 5, l = tid & 31;
    if (l == 0) { shs[w] = s; shq[w] = q; }
    __syncthreads();
    if (tid == 0) {
        float ts = 0.f, tq = 0.f;
        #pragma unroll
        for (int i = 0; i < 8; i++) { ts += shs[i]; tq += shq[i]; }
        shs[0] = ts; shq[0] = tq;
    }
    __syncthreads();

    const float mean = shs[0] * (1.0f / DD);
    const float var  = shq[0] * (1.0f / DD) - mean * mean;
    const float inv  = 1.0f / sqrtf(var + EPS);

    float4 g0 = *(const float4*)(gam + tid * 4);
    float4 g1 = *(const float4*)(gam + 1024 + tid * 4);
    float4 b0 = *(const float4*)(bet + tid * 4);
    float4 b1 = *(const float4*)(bet + 1024 + tid * 4);

    float4 o0, o1;
    o0.x = (v0.x - mean) * inv * g0.x + b0.x;
    o0.y = (v0.y - mean) * inv * g0.y + b0.y;
    o0.z = (v0.z - mean) * inv * g0.z + b0.z;
    o0.w = (v0.w - mean) * inv * g0.w + b0.w;
    o1.x = (v1.x - mean) * inv * g1.x + b1.x;
    o1.y = (v1.y - mean) * inv * g1.y + b1.y;
    o1.z = (v1.z - mean) * inv * g1.z + b1.z;
    o1.w = (v1.w - mean) * inv * g1.w + b1.w;

    float* yr = out + (size_t)row * DD;
    *(float4*)(yr + tid * 4)        = o0;
    *(float4*)(yr + 1024 + tid * 4) = o1;
}

// ---------------------------------------------------------------------------
// RoPE (in place on q,k halves of qkv)
// ---------------------------------------------------------------------------
__global__ void rope_kernel(float* __restrict__ qkv, const int* __restrict__ pid)
{
    __shared__ float sinv[64];
    const int tid = threadIdx.x;
    if (tid < 64)
        sinv[tid] = (float)exp(-((double)tid / 64.0) * 9.210340371976184);
    __syncthreads();

    const int idx = blockIdx.x * 256 + tid;
    const int i   = idx & 63;
    const int h   = (idx >> 6) & 15;
    const int row = idx >> 10;

    const float f = (float)pid[row] * sinv[i];
    float sv, cv;
    sincosf(f, &sv, &cv);

    const size_t base = (size_t)row * E3 + (size_t)h * 384;
    float q0 = qkv[base + i],       q1 = qkv[base + 64 + i];
    qkv[base + i]        = q0 * cv - q1 * sv;
    qkv[base + 64 + i]   = q1 * cv + q0 * sv;
    float k0 = qkv[base + 128 + i], k1 = qkv[base + 192 + i];
    qkv[base + 128 + i]  = k0 * cv - k1 * sv;
    qkv[base + 192 + i]  = k1 * cv + k0 * sv;
}

// ---------------------------------------------------------------------------
// Flash attention v2 (unchanged from R14-passing version): 64-q blocks,
// 64-key tiles, 256 threads, partner-warp d-split, tf32 MMA.
// ---------------------------------------------------------------------------
#define QPAD 132
#define KPAD 72
#define VPAD 136
#define FLASH_SMEM ((64*QPAD + 128*KPAD + 64*VPAD) * 4)

__global__ __launch_bounds__(256, 2)
void flash_kernel(const float* __restrict__ qkv,
                  const unsigned char* __restrict__ mask,
                  float* __restrict__ ctx)
{
    extern __shared__ float sm[];
    float* Qs = sm;                            // [64 q][QPAD]
    float* Ks = sm + 64 * QPAD;                // [128 d][KPAD], cols xor-swizzled
    float* Vs = sm + 64 * QPAD + 128 * KPAD;   // [64 key][VPAD]

    const int qblk = blockIdx.x;     // 0..31
    const int bh   = blockIdx.y;     // 0..31
    const int b = bh >> 4, h = bh & 15;
    const int tid = threadIdx.x;
    const int lane = tid & 31, wid = tid >> 5;
    const int mq = lane >> 2, kq = lane & 3;
    const int qg  = wid >> 1;        // q-row group 0..3
    const int dh2 = wid & 1;         // d half

    const float scale = 0.08838834764831845f;   // 1/sqrt(128)
    const float* qbase = qkv + (size_t)(b * SS + qblk * 64) * E3 + (size_t)h * 384;

    #pragma unroll
    for (int it = 0; it < 8; it++) {
        int idx = it * 256 + tid;
        int r = idx >> 5, c4 = (idx & 31) * 4;
        float4 v = *(const float4*)(qbase + (size_t)r * E3 + c4);
        float4 o;
        o.x = to_tf32(v.x * scale); o.y = to_tf32(v.y * scale);
        o.z = to_tf32(v.z * scale); o.w = to_tf32(v.w * scale);
        *(float4*)(Qs + r * QPAD + c4) = o;
    }

    float m0 = -1e30f, m1 = -1e30f, l0 = 0.f, l1 = 0.f;
    float O[8][4];
    #pragma unroll
    for (int d = 0; d < 8; d++)
        #pragma unroll
        for (int c = 0; c < 4; c++) O[d][c] = 0.f;

    const int qrow = qg * 16 + mq;

    for (int kb = 0; kb < 32; kb++) {
        __syncthreads();

        {
            const float* kbase = qkv + (size_t)(b * SS + kb * 64) * E3
                               + (size_t)h * 384 + 128;
            const int key = tid >> 2;
            const int ac  = (tid & 3) * 4;
            const float* kp = kbase + (size_t)key * E3 + ac;
            #pragma unroll
            for (int ch = 0; ch < 128; ch += 16) {
                float4 v = *(const float4*)(kp + ch);
                float t_[4] = {v.x, v.y, v.z, v.w};
                #pragma unroll
                for (int i = 0; i < 4; i++) {
                    int d = ch + ac + i;
                    int col = key ^ (((d >> 2) & 3) << 3);
                    Ks[d * KPAD + col] = to_tf32(t_[i]);
                }
            }
        }
        {
            const float* vbase = qkv + (size_t)(b * SS + kb * 64) * E3
                               + (size_t)h * 384 + 256;
            #pragma unroll
            for (int it = 0; it < 8; it++) {
                int idx = it * 256 + tid;
                int r = idx >> 5, c4 = (idx & 31) * 4;
                float4 v = *(const float4*)(vbase + (size_t)r * E3 + c4);
                float4 o;
                o.x = to_tf32(v.x); o.y = to_tf32(v.y);
                o.z = to_tf32(v.z); o.w = to_tf32(v.w);
                *(float4*)(Vs + r * VPAD + c4) = o;
            }
        }
        __syncthreads();

        float S[8][4];
        #pragma unroll
        for (int t = 0; t < 8; t++)
            #pragma unroll
            for (int c = 0; c < 4; c++) S[t][c] = 0.f;

        #pragma unroll
        for (int k8 = 0; k8 < 16; k8++) {
            const int kr = k8 * 8 + kq;
            uint32_t a0 = __float_as_uint(Qs[qrow * QPAD + kr]);
            uint32_t a1 = __float_as_uint(Qs[(qrow + 8) * QPAD + kr]);
            uint32_t a2 = __float_as_uint(Qs[qrow * QPAD + kr + 4]);
            uint32_t a3 = __float_as_uint(Qs[(qrow + 8) * QPAD + kr + 4]);
            const int sx0 = (((2 * k8)    ) & 3) << 3;
            const int sx1 = (((2 * k8) + 1) & 3) << 3;
            #pragma unroll
            for (int t = 0; t < 8; t++) {
                uint32_t b0 = __float_as_uint(Ks[kr * KPAD + ((t * 8 + mq) ^ sx0)]);
                uint32_t b1 = __float_as_uint(Ks[(kr + 4) * KPAD + ((t * 8 + mq) ^ sx1)]);
                MMA_TF32(S[t][0], S[t][1], S[t][2], S[t][3],
                         a0, a1, a2, a3, b0, b1);
            }
        }

        {
            const unsigned char* mbase = mask + (size_t)b * SS * SS
                + (size_t)(qblk * 64 + qrow) * SS + kb * 64;
            const unsigned char* mbase8 = mbase + (size_t)8 * SS;
            #pragma unroll
            for (int t = 0; t < 8; t++) {
                uchar2 u0 = *(const uchar2*)(mbase  + t * 8 + 2 * kq);
                uchar2 u1 = *(const uchar2*)(mbase8 + t * 8 + 2 * kq);
                if (u0.x) S[t][0] = -10000.f;
                if (u0.y) S[t][1] = -10000.f;
                if (u1.x) S[t][2] = -10000.f;
                if (u1.y) S[t][3] = -10000.f;
            }
        }

        float mi0 = -1e30f, mi1 = -1e30f;
        #pragma unroll
        for (int t = 0; t < 8; t++) {
            mi0 = fmaxf(mi0, fmaxf(S[t][0], S[t][1]));
            mi1 = fmaxf(mi1, fmaxf(S[t][2], S[t][3]));
        }
        mi0 = fmaxf(mi0, __shfl_xor_sync(0xffffffffu, mi0, 1));
        mi0 = fmaxf(mi0, __shfl_xor_sync(0xffffffffu, mi0, 2));
        mi1 = fmaxf(mi1, __shfl_xor_sync(0xffffffffu, mi1, 1));
        mi1 = fmaxf(mi1, __shfl_xor_sync(0xffffffffu, mi1, 2));

        const float mn0 = fmaxf(m0, mi0);
        const float mn1 = fmaxf(m1, mi1);
        const float f0 = fexp(m0 - mn0);
        const float f1 = fexp(m1 - mn1);
        m0 = mn0; m1 = mn1;

        float s0 = 0.f, s1 = 0.f;
        #pragma unroll
        for (int t = 0; t < 8; t++) {
            float p;
            p = fexp(S[t][0] - mn0); s0 += p; S[t][0] = to_tf32(p);
            p = fexp(S[t][1] - mn0); s0 += p; S[t][1] = to_tf32(p);
            p = fexp(S[t][2] - mn1); s1 += p; S[t][2] = to_tf32(p);
            p = fexp(S[t][3] - mn1); s1 += p; S[t][3] = to_tf32(p);
        }
        s0 += __shfl_xor_sync(0xffffffffu, s0, 1);
        s0 += __shfl_xor_sync(0xffffffffu, s0, 2);
        s1 += __shfl_xor_sync(0xffffffffu, s1, 1);
        s1 += __shfl_xor_sync(0xffffffffu, s1, 2);
        l0 = l0 * f0 + s0;
        l1 = l1 * f1 + s1;

        #pragma unroll
        for (int d = 0; d < 8; d++) {
            O[d][0] *= f0; O[d][1] *= f0;
            O[d][2] *= f1; O[d][3] *= f1;
        }

        const int srcA = (lane & ~3) | (kq >> 1);
        const int srcB = srcA + 2;
        const bool odd = (kq & 1);
        const int dbase = dh2 * 64;
        #pragma unroll
        for (int j = 0; j < 8; j++) {
            float sA0 = __shfl_sync(0xffffffffu, S[j][0], srcA);
            float sA1 = __shfl_sync(0xffffffffu, S[j][1], srcA);
            float sA2 = __shfl_sync(0xffffffffu, S[j][2], srcA);
            float sA3 = __shfl_sync(0xffffffffu, S[j][3], srcA);
            float sB0 = __shfl_sync(0xffffffffu, S[j][0], srcB);
            float sB1 = __shfl_sync(0xffffffffu, S[j][1], srcB);
            float sB2 = __shfl_sync(0xffffffffu, S[j][2], srcB);
            float sB3 = __shfl_sync(0xffffffffu, S[j][3], srcB);
            uint32_t a0 = __float_as_uint(odd ? sA1 : sA0);
            uint32_t a1 = __float_as_uint(odd ? sA3 : sA2);
            uint32_t a2 = __float_as_uint(odd ? sB1 : sB0);
            uint32_t a3 = __float_as_uint(odd ? sB3 : sB2);
            const int krow = j * 8 + kq;
            #pragma unroll
            for (int d = 0; d < 8; d++) {
                uint32_t b0 = __float_as_uint(Vs[krow * VPAD + dbase + d * 8 + mq]);
                uint32_t b1 = __float_as_uint(Vs[(krow + 4) * VPAD + dbase + d * 8 + mq]);
                MMA_TF32(O[d][0], O[d][1], O[d][2], O[d][3],
                         a0, a1, a2, a3, b0, b1);
            }
        }
    }

    const float inv0 = 1.0f / l0;
    const float inv1 = 1.0f / l1;
    const size_t r0 = (size_t)(b * SS + qblk * 64 + qg * 16 + mq);
    float* c0row = ctx + r0 * DD + h * DH + dh2 * 64;
    float* c1row = c0row + (size_t)8 * DD;
    #pragma unroll
    for (int d = 0; d < 8; d++) {
        const int col = d * 8 + 2 * kq;
        float2 o0, o1;
        o0.x = O[d][0] * inv0; o0.y = O[d][1] * inv0;
        o1.x = O[d][2] * inv1; o1.y = O[d][3] * inv1;
        *(float2*)(c0row + col) = o0;
        *(float2*)(c1row + col) = o1;
    }
}

// ---------------------------------------------------------------------------
// SwiGLU: g = silu(a) * b
// ---------------------------------------------------------------------------
__global__ void swiglu_kernel(const float* __restrict__ ab, float* __restrict__ g)
{
    const int c = blockIdx.x * 256 + threadIdx.x;
    const int r = blockIdx.y;
    const size_t base = (size_t)r * (2 * FFN);
    const float a = ab[base + c];
    const float b = ab[base + FFN + c];
    g[(size_t)r * FFN + c] = (a / (1.0f + fexp(-a))) * b;
}

// ---------------------------------------------------------------------------
// FP16 tensor-core GEMM: C = alpha*A@B (+R).
// 128x128x16 CTA tile, 256 threads = 8 warps, warp tile 64x32 via m16n8k16.
// Smem: k-pair-major half2 tiles [8 kp][136], column xor s(kp):
//   s(kp) = kp<4 ? 0 : (kp&1 ? 24 : 8)
// -> both store patterns and all fragment loads are bank-conflict-free
//    (verified per-instruction for every base residue).
// A: [M,K] row-major, B: [K,N] row-major. Dims are exact tile multiples.
// ---------------------------------------------------------------------------
#define HPAD 136

__device__ __forceinline__ int bswz(int kp) {
    return (kp < 4) ? 0 : ((kp & 1) ? 24 : 8);
}

__global__ __launch_bounds__(256, 2)
void gemm_hc(int K,
             const float* __restrict__ A, int lda,
             const float* __restrict__ B, int ldb,
             float*       __restrict__ C, int ldc,
             const float* __restrict__ R, float alpha)
{
    __shared__ __half2 Ash[2][8][HPAD];
    __shared__ __half2 Bsh[2][8][HPAD];

    const int m0  = blockIdx.y * 128;
    const int n0  = blockIdx.x * 128;
    const int tid = threadIdx.x;
    const int lane = tid & 31;
    const int wid  = tid >> 5;
    const int wm = (wid >> 2) * 64;   // 0/64
    const int wn = (wid & 3) * 32;    // 0,32,64,96
    const int kq = lane & 3;
    const int mq = lane >> 2;
    const int s4 = (kq & 1) ? 24 : 8; // swizzle for kp = kq+4

    // A loader: thread (ar 0..63, ac in {0,4,8,12}); rows ar and ar+64
    const int ar  = tid >> 2;
    const int ac  = (tid & 3) << 2;
    const int kpA = ac >> 1;                  // 0,2,4,6
    const int sA0 = bswz(kpA);
    const int sA1 = bswz(kpA + 1);
    const int cA0 = ar ^ sA0;
    const int cA1 = ar ^ sA1;

    // B loader: lane-contiguous n, k-pair pack
    const int bn  = tid & 127;
    const int bg  = tid >> 7;                 // 0/1
    const int kpB = 4 * bg;
    int cB[4];
    #pragma unroll
    for (int j = 0; j < 4; j++) cB[j] = bn ^ bswz(kpB + j);

    const float* Ag0 = A + (size_t)(m0 + ar) * lda + ac;
    const float* Ag1 = Ag0 + (size_t)64 * lda;
    const float* Bg  = B + n0 + bn;

    float acc[4][4][4];
    #pragma unroll
    for (int i = 0; i < 4; i++)
        #pragma unroll
        for (int j = 0; j < 4; j++)
            #pragma unroll
            for (int c = 0; c < 4; c++) acc[i][j][c] = 0.f;

    float4 ra0, ra1;
    float bl[4], bh[4];

#define LOAD_TILE(kt) do {                                                      \
        ra0 = *(const float4*)(Ag0 + (size_t)(kt) * 16);                        \
        ra1 = *(const float4*)(Ag1 + (size_t)(kt) * 16);                        \
        _Pragma("unroll")                                                       \
        for (int j_ = 0; j_ < 4; j_++) {                                        \
            const size_t kr_ = (size_t)((kt) * 16 + 2 * (kpB + j_)) * ldb;      \
            bl[j_] = Bg[kr_];                                                   \
            bh[j_] = Bg[kr_ + ldb];                                             \
        }                                                                       \
    } while (0)

#define STORE_TILE(buf) do {                                                    \
        Ash[buf][kpA][cA0]          = __floats2half2_rn(ra0.x, ra0.y);          \
        Ash[buf][kpA + 1][cA1]      = __floats2half2_rn(ra0.z, ra0.w);          \
        Ash[buf][kpA][cA0 + 64]     = __floats2half2_rn(ra1.x, ra1.y);          \
        Ash[buf][kpA + 1][cA1 + 64] = __floats2half2_rn(ra1.z, ra1.w);          \
        _Pragma("unroll")                                                       \
        for (int j_ = 0; j_ < 4; j_++)                                          \
            Bsh[buf][kpB + j_][cB[j_]] = __floats2half2_rn(bl[j_], bh[j_]);     \
    } while (0)

    const int T = K >> 4;
    LOAD_TILE(0);
    STORE_TILE(0);
    __syncthreads();

    for (int t = 0; t < T; ++t) {
        const int cur = t & 1;
        if (t + 1 < T) LOAD_TILE(t + 1);

        uint32_t af[4][4], bf[4][2];
        #pragma unroll
        for (int mi = 0; mi < 4; mi++) {
            const int mb = wm + mi * 16 + mq;
            af[mi][0] = *(const uint32_t*)&Ash[cur][kq][mb];
            af[mi][1] = *(const uint32_t*)&Ash[cur][kq][mb + 8];
            af[mi][2] = *(const uint32_t*)&Ash[cur][kq + 4][mb ^ s4];
            af[mi][3] = *(const uint32_t*)&Ash[cur][kq + 4][(mb + 8) ^ s4];
        }
        #pragma unroll
        for (int nj = 0; nj < 4; nj++) {
            const int nb = wn + nj * 8 + mq;
            bf[nj][0] = *(const uint32_t*)&Bsh[cur][kq][nb];
            bf[nj][1] = *(const uint32_t*)&Bsh[cur][kq + 4][nb ^ s4];
        }
        #pragma unroll
        for (int mi = 0; mi < 4; mi++)
            #pragma unroll
            for (int nj = 0; nj < 4; nj++)
                MMA_F16(acc[mi][nj][0], acc[mi][nj][1],
                        acc[mi][nj][2], acc[mi][nj][3],
                        af[mi][0], af[mi][1], af[mi][2], af[mi][3],
                        bf[nj][0], bf[nj][1]);

        if (t + 1 < T) {
            STORE_TILE(cur ^ 1);
            __syncthreads();
        }
    }

#undef LOAD_TILE
#undef STORE_TILE

    // Epilogue: c0,c1 at (mq, 2kq/2kq+1); c2,c3 at row mq+8 (same as tf32)
    #pragma unroll
    for (int mi = 0; mi < 4; mi++) {
        #pragma unroll
        for (int half = 0; half < 2; half++) {
            const int m = m0 + wm + mi * 16 + mq + half * 8;
            float* crow = C + (size_t)m * ldc;
            const float* rrow = R ? R + (size_t)m * ldc : nullptr;
            #pragma unroll
            for (int nj = 0; nj < 4; nj++) {
                const int n = n0 + wn + nj * 8 + 2 * kq;
                float2 o;
                o.x = alpha * acc[mi][nj][half * 2 + 0];
                o.y = alpha * acc[mi][nj][half * 2 + 1];
                if (R) {
                    float2 rv = *(const float2*)(rrow + n);
                    o.x += rv.x; o.y += rv.y;
                }
                *(float2*)(crow + n) = o;
            }
        }
    }
}

// ---------------------------------------------------------------------------
// Launch
// ---------------------------------------------------------------------------
extern "C" void kernel_launch(void* const* d_in, const int* in_sizes, int n_in,
                              void* d_out, int out_size)
{
    const float*         hidden = (const float*)d_in[0];
    const unsigned char* mask   = (const unsigned char*)d_in[1];
    const int*           pos    = (const int*)d_in[2];
    const float*         ln1g   = (const float*)d_in[3];
    const float*         ln1b   = (const float*)d_in[4];
    const float*         Wqkv   = (const float*)d_in[5];
    const float*         Wo     = (const float*)d_in[6];
    const float*         ln2g   = (const float*)d_in[7];
    const float*         ln2b   = (const float*)d_in[8];
    const float*         Wfi    = (const float*)d_in[9];
    const float*         Wfo    = (const float*)d_in[10];
    float*               out    = (float*)d_out;

    float *x, *qkv, *ctx, *h1, *x2, *ab, *gt;
    cudaGetSymbolAddress((void**)&x,   g_x);
    cudaGetSymbolAddress((void**)&qkv, g_qkv);
    cudaGetSymbolAddress((void**)&ctx, g_ctx);
    cudaGetSymbolAddress((void**)&h1,  g_h1);
    cudaGetSymbolAddress((void**)&x2,  g_x2);
    cudaGetSymbolAddress((void**)&ab,  g_ab);
    cudaGetSymbolAddress((void**)&gt,  g_gate);

    cudaFuncSetAttribute(flash_kernel,
                         cudaFuncAttributeMaxDynamicSharedMemorySize, FLASH_SMEM);

    // 1) LN1
    ln_kernel<<<ROWS, 256>>>(hidden, ln1g, ln1b, x);

    // 2) qkv = x @ Wqkv
    gemm_hc<<<dim3(E3 / 128, ROWS / 128), 256>>>(
        DD, x, DD, Wqkv, E3, qkv, E3, nullptr, 1.0f);

    // 3) RoPE on q,k (in place)
    rope_kernel<<<(ROWS * NH * 64) / 256, 256>>>(qkv, pos);

    // 4) fused attention -> ctx
    flash_kernel<<<dim3(SS / 64, BB * NH), 256, FLASH_SMEM>>>(qkv, mask, ctx);

    // 5) h1 = hidden + ctx @ Wo
    gemm_hc<<<dim3(DD / 128, ROWS / 128), 256>>>(
        DD, ctx, DD, Wo, DD, h1, DD, hidden, 1.0f);

    // 6) LN2
    ln_kernel<<<ROWS, 256>>>(h1, ln2g, ln2b, x2);

    // 7) ab = x2 @ Wfc_in
    gemm_hc<<<dim3((2 * FFN) / 128, ROWS / 128), 256>>>(
        DD, x2, DD, Wfi, 2 * FFN, ab, 2 * FFN, nullptr, 1.0f);

    // 8) gate = silu(a) * b
    swiglu_kernel<<<dim3(FFN / 256, ROWS), 256>>>(ab, gt);

    // 9) out = h1 + gate @ Wfc_out
    gemm_hc<<<dim3(DD / 128, ROWS / 128), 256>>>(
        FFN, gt, FFN, Wfo, DD, out, DD, h1, 1.0f);

    (void)in_sizes; (void)n_in; (void)out_size;
}